// round 17
// baseline (speedup 1.0000x reference)
#include <cuda_runtime.h>
#include <cuda_fp16.h>
#include <cstdint>

// ============================================================================
// R17: R16 + convert folded into mega as leading producer blocks:
//  launch 0: zero_cnt (counters)
//  launch 1 (mega): convert-x(64 row-blocks) + convert-W(24 row-blocks)
//                   + QKVproj(1536, spin on 1-arrival x/W block counters)
//                   + QK(1024, spin on 8-arrival Q/K row-block counters)
//  launch 2: softmax (fp16 S, coalesced)   launch 3: PV
// Counters: [0,64) x row-blocks, [64,88) W row-blocks,
//           [88,152) Q row-blocks, [152,216) K row-blocks.
// Producer-adjacent shallow chains only (R12-validated regime).
// Math identical to R16 -> rel_err 6.80e-4.
// ============================================================================

using fp16 = __half;

// ---------------- scratch ----------------------------------------------------
__device__ __align__(256) fp16 g_x[8192 * 1024];
__device__ __align__(256) fp16 g_W[3 * 1024 * 1024];
__device__ __align__(256) fp16 g_Q[8192 * 1024];
__device__ __align__(256) fp16 g_K[8192 * 1024];
__device__ __align__(256) fp16 g_Vt[4 * 1024 * 2048];        // transposed
__device__ __align__(256) fp16 g_S[4 * 2048 * 2048];         // fp16 scores
__device__ __align__(256) fp16 g_P[4 * 2048 * 2048];
__device__ int g_cnt[256];

// ---------------- PTX helpers -------------------------------------------------
__device__ __forceinline__ uint32_t smem_u32(const void* p) {
    uint32_t a;
    asm("{ .reg .u64 t; cvta.to.shared.u64 t, %1; cvt.u32.u64 %0, t; }" : "=r"(a) : "l"(p));
    return a;
}
__device__ __forceinline__ void cp16(uint32_t dst, const void* src) {
    asm volatile("cp.async.cg.shared.global [%0], [%1], 16;" :: "r"(dst), "l"(src));
}
#define CP_COMMIT() asm volatile("cp.async.commit_group;" ::: "memory")

__device__ __forceinline__ void ldm4(uint32_t* r, uint32_t a) {
    asm volatile("ldmatrix.sync.aligned.m8n8.x4.shared.b16 {%0,%1,%2,%3}, [%4];"
                 : "=r"(r[0]), "=r"(r[1]), "=r"(r[2]), "=r"(r[3]) : "r"(a));
}
__device__ __forceinline__ void mma_f16(float* c, const uint32_t* a, uint32_t b0, uint32_t b1) {
    asm volatile(
        "mma.sync.aligned.m16n8k16.row.col.f32.f16.f16.f32 "
        "{%0,%1,%2,%3}, {%4,%5,%6,%7}, {%8,%9}, {%0,%1,%2,%3};"
        : "+f"(c[0]), "+f"(c[1]), "+f"(c[2]), "+f"(c[3])
        : "r"(a[0]), "r"(a[1]), "r"(a[2]), "r"(a[3]), "r"(b0), "r"(b1));
}
__device__ __forceinline__ int ld_acq(const int* p) {
    int v;
    asm volatile("ld.acquire.gpu.global.b32 %0, [%1];" : "=r"(v) : "l"(p) : "memory");
    return v;
}
__device__ __forceinline__ void spin_until(const int* c, int target) {
    if (threadIdx.x == 0) {
        while (ld_acq(c) < target) __nanosleep(64);
    }
}
__device__ __forceinline__ void arrive(int idx) {
    __threadfence();
    __syncthreads();
    if (threadIdx.x == 0) atomicAdd(&g_cnt[idx], 1);
}

// ---------------- SMEM layout -------------------------------------------------
#define ROWB     144
#define ARR_B    (128 * ROWB)          // 18432
#define STG_B    (2 * ARR_B)           // 36864
#define SM_TOTAL (2 * STG_B)           // 73728

// ---------------- GEMM body: 128x128 tile, 256 thr, warps 2(m) x 4(n) --------
// MODE 0: QKV (z: 0->Q, 1->K, 2->V transposed) -> fp16
// MODE 1: QK  (z=batch), g_S = fp16(acc/32)
// MODE 2: PV  (z=batch), out = acc fp32
template <int MODE>
__device__ __forceinline__ void gemm_body(
    const fp16* __restrict__ A, int lda,
    const fp16* __restrict__ B, int ldb,
    int K, float* __restrict__ outp,
    int bx, int by, int z)
{
    extern __shared__ char sm[];
    const uint32_t smb = smem_u32(sm);
    const int tid = threadIdx.x, lane = tid & 31, wid = tid >> 5;
    const int wm = wid & 1, wn = wid >> 1;          // warp tile: 64x32
    const int row0 = by * 128, col0 = bx * 128;

    float acc[4][4][4];
    #pragma unroll
    for (int i = 0; i < 4; ++i)
        #pragma unroll
        for (int j = 0; j < 4; ++j)
            #pragma unroll
            for (int k = 0; k < 4; ++k) acc[i][j][k] = 0.f;

    const fp16* pa = A + (size_t)row0 * lda;
    const fp16* pb = B + (size_t)col0 * ldb;

    auto load_stage = [&](int sbuf, int k0) {
        const uint32_t b = smb + sbuf * STG_B;
        #pragma unroll
        for (int v = 0; v < 4; ++v) {
            const int idx = tid + v * 256;       // 0..1023
            const int row = idx >> 3;            // 0..127
            const int kc  = idx & 7;             // 16B unit
            const uint32_t so = row * ROWB + kc * 16;
            cp16(b + so,         pa + (size_t)row * lda + k0 + kc * 8);
            cp16(b + ARR_B + so, pb + (size_t)row * ldb + k0 + kc * 8);
        }
        CP_COMMIT();
    };

    const int ns = K >> 6;   // 64 K per stage
    load_stage(0, 0);

    const uint32_t a_off = (wm * 64 + (lane & 15)) * ROWB + (lane >> 4) * 16;
    const uint32_t b_off = ARR_B
                         + (wn * 32 + (lane & 7) + ((lane >> 4) << 3)) * ROWB
                         + ((lane >> 3) & 1) * 16;

    for (int s = 0; s < ns; ++s) {
        if (s + 1 < ns) {
            load_stage((s + 1) & 1, (s + 1) * 64);
            asm volatile("cp.async.wait_group 1;" ::: "memory");
        } else {
            asm volatile("cp.async.wait_group 0;" ::: "memory");
        }
        __syncthreads();

        const uint32_t sb = smb + (s & 1) * STG_B;
        #pragma unroll
        for (int ks = 0; ks < 4; ++ks) {         // 4 k16 slices per stage
            const uint32_t ab = sb + a_off + ks * 32;
            const uint32_t bb = sb + b_off + ks * 32;
            uint32_t af[4][4], bf[2][4];
            #pragma unroll
            for (int mt = 0; mt < 4; ++mt)
                ldm4(af[mt], ab + mt * 16 * ROWB);
            #pragma unroll
            for (int bt = 0; bt < 2; ++bt)
                ldm4(bf[bt], bb + bt * 16 * ROWB);
            #pragma unroll
            for (int mt = 0; mt < 4; ++mt)
                #pragma unroll
                for (int nt = 0; nt < 4; ++nt) {
                    const int bt = nt >> 1, h = (nt & 1) * 2;
                    mma_f16(acc[mt][nt], af[mt], bf[bt][h], bf[bt][h + 1]);
                }
        }
        __syncthreads();
    }

    // ---- epilogue ----
    const int gr0 = row0 + wm * 64 + (lane >> 2);
    const int gc0 = col0 + wn * 32 + (lane & 3) * 2;

    #pragma unroll
    for (int mt = 0; mt < 4; ++mt)
        #pragma unroll
        for (int nt = 0; nt < 4; ++nt) {
            const int gr = gr0 + mt * 16;
            const int gc = gc0 + nt * 8;
            const float* c = acc[mt][nt];
            if (MODE == 0) {
                if (z == 2) {            // V: fp16, transposed Vt[(b*1024+n)][t]
                    const int b = gr >> 11, t = gr & 2047;
                    const size_t o = ((size_t)(b * 1024 + gc)) * 2048 + t;
                    g_Vt[o]            = __float2half(c[0]);
                    g_Vt[o + 2048]     = __float2half(c[1]);
                    g_Vt[o + 8]        = __float2half(c[2]);
                    g_Vt[o + 2048 + 8] = __float2half(c[3]);
                } else {                 // Q or K: fp16 row-major
                    fp16* d = (z == 0) ? g_Q : g_K;
                    const size_t o = (size_t)gr * 1024 + gc;
                    *(__half2*)(d + o)            = __floats2half2_rn(c[0], c[1]);
                    *(__half2*)(d + o + 8 * 1024) = __floats2half2_rn(c[2], c[3]);
                }
            } else if (MODE == 1) {      // S: fp16
                fp16* p = g_S + ((size_t)z << 22) + (size_t)gr * 2048 + gc;
                *(__half2*)p             = __floats2half2_rn(c[0] * 0.03125f, c[1] * 0.03125f);
                *(__half2*)(p + 8*2048)  = __floats2half2_rn(c[2] * 0.03125f, c[3] * 0.03125f);
            } else {
                float* p = outp + ((size_t)z << 21) + (size_t)gr * 1024 + gc;
                *(float2*)p              = make_float2(c[0], c[1]);
                *(float2*)(p + 8 * 1024) = make_float2(c[2], c[3]);
            }
        }
}

// ---------------- convert one 128x1024 fp32 row-block to fp16 -----------------
__device__ __forceinline__ void convert_block(const float* __restrict__ src,
                                              fp16* __restrict__ dst)
{
    // 131072 elements = 32768 float4; 256 threads x 128 iters
    const int tid = threadIdx.x;
    #pragma unroll 4
    for (int i = tid; i < 32768; i += 256) {
        float4 v = *(const float4*)(src + (size_t)i * 4);
        __half2* d = (__half2*)(dst + (size_t)i * 4);
        d[0] = __floats2half2_rn(v.x, v.y);
        d[1] = __floats2half2_rn(v.z, v.w);
    }
}

// ---------------- launch 1: convert + QKVproj + QK ----------------------------
__global__ void __launch_bounds__(256)
mega_kernel(const float* __restrict__ x, const float* __restrict__ Wq,
            const float* __restrict__ Wk, const float* __restrict__ Wv)
{
    const int b = blockIdx.x;
    if (b < 64) {                       // ---- convert x row-block b ----
        convert_block(x + (size_t)b * 131072, g_x + (size_t)b * 131072);
        arrive(b);
    } else if (b < 88) {                // ---- convert W row-block ----
        const int j = b - 64;           // 0..23
        const int w = j >> 3, blk = j & 7;
        const float* src = (w == 0) ? Wq : (w == 1) ? Wk : Wv;
        convert_block(src + (size_t)blk * 131072,
                      g_W + (size_t)w * 1048576 + (size_t)blk * 131072);
        arrive(64 + j);
    } else if (b < 1624) {              // ---- QKV projections ----
        const int j = b - 88;
        const int z = j >> 9, r = j & 511;      // z in 0..2
        const int bx = r & 7, by = r >> 3;
        spin_until(&g_cnt[by], 1);              // x row-block converted
        spin_until(&g_cnt[64 + z * 8 + bx], 1); // W row-block converted
        __syncthreads();
        gemm_body<0>(g_x, 1024, g_W + (size_t)z * 1048576, 1024,
                     1024, nullptr, bx, by, z);
        if (z < 2) arrive(88 + z * 64 + by);    // Q/K row-block (8 arrivals)
    } else {                            // ---- QK tiles ----
        const int j = b - 1624;
        const int z = j >> 8, by = (j >> 4) & 15, bx = j & 15;
        spin_until(&g_cnt[88 + z * 16 + by], 8);        // Q row-block
        spin_until(&g_cnt[152 + z * 16 + bx], 8);       // K row-block
        __syncthreads();
        const size_t bo = (size_t)z << 21;
        gemm_body<1>(g_Q + bo, 1024, g_K + bo, 1024, 1024, nullptr, bx, by, z);
    }
}

// ---------------- softmax: fp16 S in, fp16 P out, fully coalesced -------------
__global__ void __launch_bounds__(256)
softmax_kernel()
{
    const size_t ro = (size_t)blockIdx.x * 2048;
    const int t = threadIdx.x;
    __shared__ float red[8];

    uint4 raw = *(const uint4*)(g_S + ro + t * 8);
    float v[8];
    {
        const __half2* h2 = (const __half2*)&raw;
        #pragma unroll
        for (int i = 0; i < 4; ++i) {
            float2 f = __half22float2(h2[i]);
            v[i * 2] = f.x;
            v[i * 2 + 1] = f.y;
        }
    }

    float m = -1e30f;
    #pragma unroll
    for (int i = 0; i < 8; ++i) m = fmaxf(m, v[i]);
    #pragma unroll
    for (int o = 16; o; o >>= 1) m = fmaxf(m, __shfl_xor_sync(0xffffffffu, m, o));
    if ((t & 31) == 0) red[t >> 5] = m;
    __syncthreads();
    m = red[0];
    #pragma unroll
    for (int i = 1; i < 8; ++i) m = fmaxf(m, red[i]);
    __syncthreads();

    float s = 0.f;
    #pragma unroll
    for (int i = 0; i < 8; ++i) {
        v[i] = __expf(v[i] - m);
        s += v[i];
    }
    #pragma unroll
    for (int o = 16; o; o >>= 1) s += __shfl_xor_sync(0xffffffffu, s, o);
    if ((t & 31) == 0) red[t >> 5] = s;
    __syncthreads();
    s = red[0];
    #pragma unroll
    for (int i = 1; i < 8; ++i) s += red[i];

    const float inv = 1.0f / s;
    uint4 outw;
    __half2* o2 = (__half2*)&outw;
    #pragma unroll
    for (int i = 0; i < 4; ++i)
        o2[i] = __floats2half2_rn(v[i * 2] * inv, v[i * 2 + 1] * inv);
    *(uint4*)(g_P + ro + t * 8) = outw;
}

// ---------------- launch 2: PV (standard grid) --------------------------------
__global__ void __launch_bounds__(256)
pv_kernel(float* __restrict__ out)
{
    const size_t ao = (size_t)blockIdx.z << 22;   // b*2048*2048
    const size_t bo = (size_t)blockIdx.z << 21;   // b*1024*2048
    gemm_body<2>(g_P + ao, 2048, g_Vt + bo, 2048, 2048, out,
                 blockIdx.x, blockIdx.y, blockIdx.z);
}

// ---------------- counter zeroing ---------------------------------------------
__global__ void zero_cnt_kernel()
{
    if (threadIdx.x < 256) g_cnt[threadIdx.x] = 0;
}

// ---------------- launch ------------------------------------------------------
extern "C" void kernel_launch(void* const* d_in, const int* in_sizes, int n_in,
                              void* d_out, int out_size)
{
    const float* x  = (const float*)d_in[0];
    const float* Wq = (const float*)d_in[1];
    const float* Wk = (const float*)d_in[2];
    const float* Wv = (const float*)d_in[3];
    float* out = (float*)d_out;

    cudaFuncSetAttribute(mega_kernel, cudaFuncAttributeMaxDynamicSharedMemorySize, SM_TOTAL);
    cudaFuncSetAttribute(pv_kernel,   cudaFuncAttributeMaxDynamicSharedMemorySize, SM_TOTAL);

    zero_cnt_kernel<<<1, 256>>>();

    // convert(88) + QKVproj(1536) + QK(1024)
    mega_kernel<<<2648, 256, SM_TOTAL>>>(x, Wq, Wk, Wv);

    softmax_kernel<<<4 * 2048, 256>>>();

    dim3 g3(8, 16, 4);    // PV
    pv_kernel<<<g3, 256, SM_TOTAL>>>(out);
}